// round 1
// baseline (speedup 1.0000x reference)
#include <cuda_runtime.h>
#include <cuda_bf16.h>
#include <math.h>

// FusionHead: B x {2-token transformer block + heads}, fully fused, fp32 with
// packed f32x2 FFMA2 inner loops (2x fp32 FMA throughput on sm_103a).
//
// Layout per CTA: 16 batch rows -> 32 token-rows (token-major: tr = t*16 + r).
// smem: SA[32][192] residual stream, SB[32][576] scratch (qkv/ffn/etc),
//       SZ[16][192] pooled z.  Total 110,592 B -> 2 CTAs/SM.

#define D 192
#define ROWS 16           // batch rows per CTA
#define TOK 32            // token rows per CTA
#define THREADS 256

typedef unsigned long long u64;

__device__ __forceinline__ void fma2(u64 &d, const u64 a, const u64 b) {
    asm("fma.rn.f32x2 %0, %1, %2, %0;" : "+l"(d) : "l"(a), "l"(b));
}
__device__ __forceinline__ float hsum2(const u64 v) {
    float lo, hi;
    asm("mov.b64 {%0, %1}, %2;" : "=f"(lo), "=f"(hi) : "l"(v));
    return lo + hi;
}

// Register-tiled GEMM stage over smem activations.
// Computes O[r][c] = act(sum_k A[r][k]*W[c][k] + bias[c] (+ R[r][c]))
// Thread grid: tx = lane (32 cols -> 2 cols per thread per 64-col block),
// rowbase..rowbase+NR-1 rows per thread. N % 64 == 0, K % 4 == 0.
template<int NR, bool RELU>
__device__ __forceinline__ void gemm_stage(
    const float* __restrict__ W, const float* __restrict__ bias,
    const float* __restrict__ A, int lda,
    float* __restrict__ O, int ldo,
    const float* __restrict__ R, int ldr,
    int N, int K, int tx, int rowbase)
{
    const int K4 = K >> 2;
    for (int cb = 0; cb < N; cb += 64) {
        const int c0 = cb + tx, c1 = c0 + 32;
        const ulonglong2* __restrict__ w0 =
            reinterpret_cast<const ulonglong2*>(W + (size_t)c0 * K);
        const ulonglong2* __restrict__ w1 =
            reinterpret_cast<const ulonglong2*>(W + (size_t)c1 * K);
        const ulonglong2* __restrict__ a[NR];
        #pragma unroll
        for (int r = 0; r < NR; r++)
            a[r] = reinterpret_cast<const ulonglong2*>(A + (rowbase + r) * lda);

        u64 acc0[NR], acc1[NR];
        #pragma unroll
        for (int r = 0; r < NR; r++) { acc0[r] = 0ULL; acc1[r] = 0ULL; }

        #pragma unroll 4
        for (int k = 0; k < K4; k++) {
            const ulonglong2 wa = w0[k];
            const ulonglong2 wb = w1[k];
            #pragma unroll
            for (int r = 0; r < NR; r++) {
                const ulonglong2 av = a[r][k];
                fma2(acc0[r], av.x, wa.x);
                fma2(acc0[r], av.y, wa.y);
                fma2(acc1[r], av.x, wb.x);
                fma2(acc1[r], av.y, wb.y);
            }
        }
        const float b0 = bias[c0], b1 = bias[c1];
        #pragma unroll
        for (int r = 0; r < NR; r++) {
            float v0 = hsum2(acc0[r]) + b0;
            float v1 = hsum2(acc1[r]) + b1;
            if (R) {
                v0 += R[(rowbase + r) * ldr + c0];
                v1 += R[(rowbase + r) * ldr + c1];
            }
            if (RELU) { v0 = fmaxf(v0, 0.f); v1 = fmaxf(v1, 0.f); }
            O[(rowbase + r) * ldo + c0] = v0;
            O[(rowbase + r) * ldo + c1] = v1;
        }
    }
}

// LayerNorm over 192 dims for `nrows` token-rows (8 warps, 1 row per warp/iter).
__device__ __forceinline__ void layernorm_rows(
    const float* __restrict__ src, int lds,
    float* __restrict__ dst, int ldd,
    const float* __restrict__ g, const float* __restrict__ b,
    int tid)
{
    const int warp = tid >> 5, lane = tid & 31;
    for (int tr = warp; tr < TOK; tr += 8) {
        const float* x = src + tr * lds;
        float v[6], s = 0.f, sq = 0.f;
        #pragma unroll
        for (int j = 0; j < 6; j++) {
            v[j] = x[lane + 32 * j];
            s += v[j];
            sq += v[j] * v[j];
        }
        #pragma unroll
        for (int o = 16; o; o >>= 1) {
            s  += __shfl_xor_sync(0xffffffffu, s,  o);
            sq += __shfl_xor_sync(0xffffffffu, sq, o);
        }
        const float mean = s * (1.f / 192.f);
        const float var  = sq * (1.f / 192.f) - mean * mean;
        const float rs   = rsqrtf(var + 1e-5f);
        #pragma unroll
        for (int j = 0; j < 6; j++) {
            const int c = lane + 32 * j;
            dst[tr * ldd + c] = (v[j] - mean) * rs * g[c] + b[c];
        }
    }
}

__global__ __launch_bounds__(THREADS, 2)
void fusion_head_kernel(
    const float* __restrict__ perc, const float* __restrict__ tech,
    const float* __restrict__ Wp,   const float* __restrict__ bp,
    const float* __restrict__ Wt,   const float* __restrict__ bt,
    const float* __restrict__ in_w, const float* __restrict__ in_b,
    const float* __restrict__ out_w,const float* __restrict__ out_b,
    const float* __restrict__ ffn_w1, const float* __restrict__ ffn_b1,
    const float* __restrict__ ffn_w2, const float* __restrict__ ffn_b2,
    const float* __restrict__ ln1_g, const float* __restrict__ ln1_b,
    const float* __restrict__ ln2_g, const float* __restrict__ ln2_b,
    const float* __restrict__ cls_w1, const float* __restrict__ cls_b1,
    const float* __restrict__ cls_w2, const float* __restrict__ cls_b2,
    const float* __restrict__ fp_w,   const float* __restrict__ fp_b,
    float* __restrict__ out, int B)
{
    extern __shared__ float smem[];
    float* SA = smem;                 // [32][192]
    float* SB = smem + TOK * D;       // [32][576]
    float* SZ = SB + TOK * 576;       // [16][192]

    const int tid = threadIdx.x;
    const int tx = tid & 31, ty = tid >> 5;
    const int rowbase = ty * 4;
    const int block0 = blockIdx.x * ROWS;

    // ---- stage 0: stage inputs into SB[tr][0:192] (token-major) ----
    for (int i = tid; i < TOK * 48; i += THREADS) {
        const int tr = i / 48, k4 = i % 48;
        const int r = (tr < ROWS) ? tr : (tr - ROWS);
        int gr = block0 + r;
        if (gr >= B) gr = B - 1;
        const float* src = (tr < ROWS) ? (perc + (size_t)gr * D)
                                       : (tech + (size_t)gr * D);
        reinterpret_cast<float4*>(SB + tr * 576)[k4] =
            reinterpret_cast<const float4*>(src)[k4];
    }
    __syncthreads();

    // ---- stage 1: input projections -> SA (token 0: Wp, token 1: Wt) ----
    {
        const float* W  = (ty < 4) ? Wp : Wt;
        const float* bb = (ty < 4) ? bp : bt;
        gemm_stage<4, false>(W, bb, SB, 576, SA, D, nullptr, 0, D, D, tx, rowbase);
    }
    __syncthreads();

    // ---- stage 2: packed QKV -> SB[tr][0:576] ----
    gemm_stage<4, false>(in_w, in_b, SA, D, SB, 576, nullptr, 0, 576, D, tx, rowbase);
    __syncthreads();

    // ---- stage 3: 2-token, 3-head attention; ctx overwrites q slots ----
    if (tid < ROWS * 6) {
        const int r = tid / 6, rem = tid % 6;
        const int t = rem & 1, h = rem >> 1;
        const float* q  = SB + (t * ROWS + r) * 576 + h * 64;
        const float* k0 = SB + r * 576 + 192 + h * 64;
        const float* k1 = SB + (ROWS + r) * 576 + 192 + h * 64;
        const float* v0 = SB + r * 576 + 384 + h * 64;
        const float* v1 = SB + (ROWS + r) * 576 + 384 + h * 64;
        float s0 = 0.f, s1 = 0.f;
        #pragma unroll 8
        for (int d = 0; d < 64; d++) {
            const float qd = q[d];
            s0 += qd * k0[d];
            s1 += qd * k1[d];
        }
        s0 *= 0.125f; s1 *= 0.125f;
        const float m = fmaxf(s0, s1);
        const float e0 = expf(s0 - m), e1 = expf(s1 - m);
        const float inv = 1.f / (e0 + e1);
        const float a0 = e0 * inv, a1 = e1 * inv;
        float* ctx = SB + (t * ROWS + r) * 576 + h * 64;  // q slot
        #pragma unroll 8
        for (int d = 0; d < 64; d++) ctx[d] = a0 * v0[d] + a1 * v1[d];
    }
    __syncthreads();

    // ---- stage 4: out-proj + residual(seq in SA) -> SB[tr][384:576] ----
    gemm_stage<4, false>(out_w, out_b, SB, 576, SB + 384, 576, SA, D, D, D, tx, rowbase);
    __syncthreads();

    // ---- stage 5: LN1 -> SA ----
    layernorm_rows(SB + 384, 576, SA, D, ln1_g, ln1_b, tid);
    __syncthreads();

    // ---- stage 6: FFN up + ReLU -> SB[tr][0:384] ----
    gemm_stage<4, true>(ffn_w1, ffn_b1, SA, D, SB, 576, nullptr, 0, 384, D, tx, rowbase);
    __syncthreads();

    // ---- stage 7: FFN down + residual(SA) -> SB[tr][384:576] ----
    gemm_stage<4, false>(ffn_w2, ffn_b2, SB, 576, SB + 384, 576, SA, D, D, 384, tx, rowbase);
    __syncthreads();

    // ---- stage 8: LN2 -> SA ----
    layernorm_rows(SB + 384, 576, SA, D, ln2_g, ln2_b, tid);
    __syncthreads();

    // ---- stage 9: z = mean over 2 tokens -> SZ ----
    for (int i = tid; i < ROWS * 48; i += THREADS) {
        const int r = i / 48, k4 = i % 48;
        const float4 x0 = reinterpret_cast<const float4*>(SA + r * D)[k4];
        const float4 x1 = reinterpret_cast<const float4*>(SA + (ROWS + r) * D)[k4];
        float4 z;
        z.x = 0.5f * (x0.x + x1.x);
        z.y = 0.5f * (x0.y + x1.y);
        z.z = 0.5f * (x0.z + x1.z);
        z.w = 0.5f * (x0.w + x1.w);
        reinterpret_cast<float4*>(SZ + r * D)[k4] = z;
    }
    __syncthreads();

    // ---- stage 10: cls hidden (relu) -> SB[r][0:192]; fp -> SB[r][192:320] ----
    gemm_stage<2, true >(cls_w1, cls_b1, SZ, D, SB,       576, nullptr, 0, D,   D, tx, ty * 2);
    gemm_stage<2, false>(fp_w,   fp_b,   SZ, D, SB + 192, 576, nullptr, 0, 128, D, tx, ty * 2);
    __syncthreads();

    // ---- stage 11: cls logits + sigmoid -> out[j*B + row] ----
    if (tid < ROWS * 3) {
        const int r = tid / 3, j = tid % 3;
        const int gr = block0 + r;
        if (gr < B) {
            const float* hrow = SB + r * 576;
            const float* w = cls_w2 + j * D;
            float s = cls_b2[j];
            #pragma unroll 8
            for (int k = 0; k < D; k++) s += hrow[k] * w[k];
            out[(size_t)j * B + gr] = 1.f / (1.f + expf(-s));
        }
    }

    // ---- stage 12: fingerprint L2-normalize -> out[3B + row*128 + c] ----
    {
        const int warp = ty, lane = tx;
        #pragma unroll
        for (int rr = 0; rr < 2; rr++) {
            const int r = warp * 2 + rr;
            const int gr = block0 + r;
            const float* f = SB + r * 576 + 192;
            float v[4], sq = 0.f;
            #pragma unroll
            for (int j = 0; j < 4; j++) {
                v[j] = f[lane + 32 * j];
                sq += v[j] * v[j];
            }
            #pragma unroll
            for (int o = 16; o; o >>= 1)
                sq += __shfl_xor_sync(0xffffffffu, sq, o);
            const float inv = 1.f / fmaxf(sqrtf(sq), 1e-12f);
            if (gr < B) {
                float* o = out + (size_t)3 * B + (size_t)gr * 128;
                #pragma unroll
                for (int j = 0; j < 4; j++) o[lane + 32 * j] = v[j] * inv;
            }
        }
    }
}

extern "C" void kernel_launch(void* const* d_in, const int* in_sizes, int n_in,
                              void* d_out, int out_size)
{
    const float* perc   = (const float*)d_in[0];
    const float* tech   = (const float*)d_in[1];
    const float* Wp     = (const float*)d_in[2];
    const float* bp     = (const float*)d_in[3];
    const float* Wt     = (const float*)d_in[4];
    const float* bt     = (const float*)d_in[5];
    const float* in_w   = (const float*)d_in[6];
    const float* in_b   = (const float*)d_in[7];
    const float* out_w  = (const float*)d_in[8];
    const float* out_b  = (const float*)d_in[9];
    const float* ffn_w1 = (const float*)d_in[10];
    const float* ffn_b1 = (const float*)d_in[11];
    const float* ffn_w2 = (const float*)d_in[12];
    const float* ffn_b2 = (const float*)d_in[13];
    const float* ln1_g  = (const float*)d_in[14];
    const float* ln1_b  = (const float*)d_in[15];
    const float* ln2_g  = (const float*)d_in[16];
    const float* ln2_b  = (const float*)d_in[17];
    const float* cls_w1 = (const float*)d_in[18];
    const float* cls_b1 = (const float*)d_in[19];
    const float* cls_w2 = (const float*)d_in[20];
    const float* cls_b2 = (const float*)d_in[21];
    const float* fp_w   = (const float*)d_in[22];
    const float* fp_b   = (const float*)d_in[23];

    const int B = in_sizes[0] / D;
    const size_t SMEM = (size_t)(TOK * D + TOK * 576 + ROWS * D) * sizeof(float);

    cudaFuncSetAttribute(fusion_head_kernel,
                         cudaFuncAttributeMaxDynamicSharedMemorySize, (int)SMEM);

    const int grid = (B + ROWS - 1) / ROWS;
    fusion_head_kernel<<<grid, THREADS, SMEM>>>(
        perc, tech, Wp, bp, Wt, bt, in_w, in_b, out_w, out_b,
        ffn_w1, ffn_b1, ffn_w2, ffn_b2, ln1_g, ln1_b, ln2_g, ln2_b,
        cls_w1, cls_b1, cls_w2, cls_b2, fp_w, fp_b,
        (float*)d_out, B);
}